// round 2
// baseline (speedup 1.0000x reference)
#include <cuda_runtime.h>
#include <math.h>

#define Bsz 4
#define Ssz 8192
#define Dsz 1024
#define Nsz 12
#define NROWS (Bsz*Ssz)

// Scratch (allocation-free rule: __device__ globals)
__device__ float g_w[NROWS * Nsz];          // normalized splat weights [row][n]
__device__ float g_U[Bsz * Nsz * Dsz];      // U[b,n,d] = sum_s w * x
__device__ float g_SV[Bsz * Nsz * Dsz];     // SV = U @ Wv^T
__device__ float g_T[Bsz * Nsz * Dsz];      // T  = SV @ Wo^T
__device__ float g_params[3 * Nsz];         // [0:12) c2, [12:24) 0.5/s^2, [24:36) amp

// ---------------------------------------------------------------------------
// Per-splat parameters: c2[n], 0.5/sigma^2[n], sigmoid(amp)[n]
// ---------------------------------------------------------------------------
__global__ void prep_kernel(const float* __restrict__ centers,
                            const float* __restrict__ scales,
                            const float* __restrict__ amps) {
    int t = threadIdx.x, warp = t >> 5, lane = t & 31;
    if (warp < Nsz) {
        float s = 0.f;
        for (int j = lane; j < Dsz; j += 32) {
            float c = centers[warp * Dsz + j];
            s += c * c;
        }
        #pragma unroll
        for (int o = 16; o > 0; o >>= 1) s += __shfl_down_sync(0xffffffffu, s, o);
        if (lane == 0) {
            g_params[warp] = s;
            float sc = expf(scales[warp]);
            sc = fminf(fmaxf(sc, 0.1f), 2.0f);
            g_params[Nsz + warp] = 0.5f / (sc * sc);
            g_params[2 * Nsz + warp] = 1.f / (1.f + expf(-amps[warp]));
        }
    }
}

__global__ void zero_kernel() {
    int i = blockIdx.x * blockDim.x + threadIdx.x;
    if (i < Bsz * Nsz * Dsz) { g_U[i] = 0.f; g_SV[i] = 0.f; g_T[i] = 0.f; }
}

// ---------------------------------------------------------------------------
// w[row][n]: one block (128 thr) per row; 13 simultaneous dot products
// ---------------------------------------------------------------------------
__global__ void compute_w_kernel(const float* __restrict__ x,
                                 const float* __restrict__ centers) {
    int row = blockIdx.x;
    const float* xr = x + (size_t)row * Dsz;
    int t = threadIdx.x;  // 128
    float p[13];
    #pragma unroll
    for (int i = 0; i < 13; i++) p[i] = 0.f;
    #pragma unroll
    for (int j = 0; j < 8; j++) {
        int d = t + j * 128;
        float xv = __ldg(&xr[d]);
        p[12] += xv * xv;
        #pragma unroll
        for (int n = 0; n < Nsz; n++) p[n] += xv * __ldg(&centers[n * Dsz + d]);
    }
    #pragma unroll
    for (int o = 16; o > 0; o >>= 1) {
        #pragma unroll
        for (int i = 0; i < 13; i++) p[i] += __shfl_down_sync(0xffffffffu, p[i], o);
    }
    __shared__ float sp[4][13];
    int warp = t >> 5, lane = t & 31;
    if (lane == 0) {
        #pragma unroll
        for (int i = 0; i < 13; i++) sp[warp][i] = p[i];
    }
    __syncthreads();
    if (t == 0) {
        float x2 = sp[0][12] + sp[1][12] + sp[2][12] + sp[3][12];
        float g[Nsz];
        float sum = 0.f;
        #pragma unroll
        for (int n = 0; n < Nsz; n++) {
            float xc = sp[0][n] + sp[1][n] + sp[2][n] + sp[3][n];
            float d2 = fmaxf(x2 + g_params[n] - 2.f * xc, 0.f);
            float gg = expf(-d2 * g_params[Nsz + n]) * g_params[2 * Nsz + n];
            g[n] = gg;
            sum += gg;
        }
        float inv = 1.f / fmaxf(sum, 1e-8f);
        #pragma unroll
        for (int n = 0; n < Nsz; n++) g_w[(size_t)row * Nsz + n] = g[n] * inv;
    }
}

// ---------------------------------------------------------------------------
// U[b,n,d] = sum_s w[b,s,n] * x[b,s,d].  Grid: (d_tile=8, s_chunk=16, b=4).
// w chunk staged in smem; 12 accumulators/thread; atomic flush.
// ---------------------------------------------------------------------------
__global__ void accum_U_kernel(const float* __restrict__ x) {
    __shared__ float ws[512 * Nsz];  // 24 KB
    int dt = blockIdx.x;   // 0..7
    int sc = blockIdx.y;   // 0..15
    int b  = blockIdx.z;   // 0..3
    int t  = threadIdx.x;  // 128
    int d  = dt * 128 + t;
    int s0 = sc * 512;

    const float* wg = g_w + ((size_t)(b * Ssz + s0)) * Nsz;
    for (int i = t; i < 512 * Nsz; i += 128) ws[i] = wg[i];
    __syncthreads();

    const float* xb = x + ((size_t)(b * Ssz + s0)) * Dsz + d;
    float acc[Nsz];
    #pragma unroll
    for (int n = 0; n < Nsz; n++) acc[n] = 0.f;

    for (int s = 0; s < 512; s++) {
        float xv = __ldg(&xb[(size_t)s * Dsz]);
        #pragma unroll
        for (int n = 0; n < Nsz; n++) acc[n] += ws[s * Nsz + n] * xv;
    }
    #pragma unroll
    for (int n = 0; n < Nsz; n++)
        atomicAdd(&g_U[((size_t)b * Nsz + n) * Dsz + d], acc[n]);
}

// ---------------------------------------------------------------------------
// Tiny GEMM: C[m,e] += sum_k A[m,k] * W[e,k],  M=48, E=1024, K=1024.
// Grid: (16 e-tiles of 64, 16 k-chunks of 64), K-split via atomics.
// phase 0: A=g_U  -> C=g_SV  (W = w_value)
// phase 1: A=g_SV -> C=g_T   (W = w_output)
// ---------------------------------------------------------------------------
__global__ void small_gemm_kernel(const float* __restrict__ W, int phase) {
    const float* A = phase ? g_SV : g_U;
    float* C = phase ? g_T : g_SV;
    __shared__ float As[64][49];   // [kk][m], padded
    __shared__ float Ws[64][66];   // [kk][e], padded (even pad -> float2 aligned)
    int e0 = blockIdx.x * 64;
    int k0 = blockIdx.y * 64;
    int t = threadIdx.x;  // 256

    for (int idx = t; idx < 48 * 64; idx += 256) {
        int m = idx >> 6, kk = idx & 63;
        As[kk][m] = A[(size_t)m * Dsz + k0 + kk];
    }
    for (int idx = t; idx < 64 * 64; idx += 256) {
        int e = idx >> 6, kk = idx & 63;
        Ws[kk][e] = W[(size_t)(e0 + e) * Dsz + k0 + kk];
    }
    __syncthreads();

    int ty = t >> 5;   // 0..7 -> 6 m-rows each
    int tx = t & 31;   // 0..31 -> 2 e-cols each
    float acc[6][2];
    #pragma unroll
    for (int i = 0; i < 6; i++) { acc[i][0] = 0.f; acc[i][1] = 0.f; }

    for (int kk = 0; kk < 64; kk++) {
        float a[6];
        #pragma unroll
        for (int i = 0; i < 6; i++) a[i] = As[kk][ty * 6 + i];
        float2 wv = *(const float2*)&Ws[kk][tx * 2];
        #pragma unroll
        for (int i = 0; i < 6; i++) {
            acc[i][0] += a[i] * wv.x;
            acc[i][1] += a[i] * wv.y;
        }
    }
    #pragma unroll
    for (int i = 0; i < 6; i++) {
        int m = ty * 6 + i;
        atomicAdd(&C[(size_t)m * Dsz + e0 + tx * 2 + 0], acc[i][0]);
        atomicAdd(&C[(size_t)m * Dsz + e0 + tx * 2 + 1], acc[i][1]);
    }
}

// ---------------------------------------------------------------------------
// final[b,s,:] = sum_n w[b,s,n] * T[b,n,:].  T[b] staged in 48KB smem.
// Grid: (256 row-chunks of 32, 4 batches), 256 thr, float4 stores.
// ---------------------------------------------------------------------------
__global__ void expand_kernel(float* __restrict__ out) {
    __shared__ float Ts[Nsz][Dsz];  // 48 KB exactly
    int b  = blockIdx.y;
    int r0 = blockIdx.x * 32;
    int t  = threadIdx.x;  // 256

    for (int idx = t; idx < Nsz * Dsz; idx += 256)
        Ts[idx >> 10][idx & 1023] = g_T[(size_t)b * Nsz * Dsz + idx];
    __syncthreads();

    int e = t * 4;
    for (int r = 0; r < 32; r++) {
        size_t row = (size_t)b * Ssz + r0 + r;
        const float* wr = g_w + row * Nsz;
        float4 o = make_float4(0.f, 0.f, 0.f, 0.f);
        #pragma unroll
        for (int n = 0; n < Nsz; n++) {
            float wv = __ldg(&wr[n]);
            float4 tv = *(const float4*)&Ts[n][e];
            o.x += wv * tv.x;
            o.y += wv * tv.y;
            o.z += wv * tv.z;
            o.w += wv * tv.w;
        }
        *(float4*)&out[row * Dsz + e] = o;
    }
}

extern "C" void kernel_launch(void* const* d_in, const int* in_sizes, int n_in,
                              void* d_out, int out_size) {
    const float* x        = (const float*)d_in[0];
    const float* centers  = (const float*)d_in[1];
    const float* scales   = (const float*)d_in[2];
    const float* amps     = (const float*)d_in[3];
    const float* w_value  = (const float*)d_in[4];
    const float* w_output = (const float*)d_in[5];
    float* out = (float*)d_out;

    prep_kernel<<<1, 384>>>(centers, scales, amps);
    zero_kernel<<<(Bsz * Nsz * Dsz + 255) / 256, 256>>>();
    compute_w_kernel<<<NROWS, 128>>>(x, centers);
    accum_U_kernel<<<dim3(8, 16, 4), 128>>>(x);
    small_gemm_kernel<<<dim3(16, 16), 256>>>(w_value, 0);
    small_gemm_kernel<<<dim3(16, 16), 256>>>(w_output, 1);
    expand_kernel<<<dim3(Ssz / 32, Bsz), 256>>>(out);
}

// round 3
// speedup vs baseline: 1.3695x; 1.3695x over previous
#include <cuda_runtime.h>
#include <math.h>

#define Bsz 4
#define Ssz 8192
#define Dsz 1024
#define Nsz 12
#define NROWS (Bsz*Ssz)
#define SC_NCHUNK 64
#define SC_CHUNK 128          // 8192/64
#define CW_ROWS 32

// Scratch (allocation-free rule: __device__ globals)
__device__ float g_w[NROWS * Nsz];                        // normalized weights [row][n]
__device__ float g_Upart[SC_NCHUNK * Bsz * Nsz * Dsz];    // stage-1 partials (12.6 MB)
__device__ float g_U[Bsz * Nsz * Dsz];
__device__ float g_SV[Bsz * Nsz * Dsz];
__device__ float g_T[Bsz * Nsz * Dsz];
__device__ float g_params[3 * Nsz];                       // c2 | 0.5/s^2 | sigmoid(amp)

// ---------------------------------------------------------------------------
__global__ void prep_kernel(const float* __restrict__ centers,
                            const float* __restrict__ scales,
                            const float* __restrict__ amps) {
    int t = threadIdx.x, warp = t >> 5, lane = t & 31;
    if (warp < Nsz) {
        float s = 0.f;
        for (int j = lane; j < Dsz; j += 32) {
            float c = centers[warp * Dsz + j];
            s += c * c;
        }
        #pragma unroll
        for (int o = 16; o > 0; o >>= 1) s += __shfl_down_sync(0xffffffffu, s, o);
        if (lane == 0) {
            g_params[warp] = s;
            float sc = expf(scales[warp]);
            sc = fminf(fmaxf(sc, 0.1f), 2.0f);
            g_params[Nsz + warp] = 0.5f / (sc * sc);
            g_params[2 * Nsz + warp] = 1.f / (1.f + expf(-amps[warp]));
        }
    }
}

__global__ void zero_kernel() {
    int i = blockIdx.x * blockDim.x + threadIdx.x;
    if (i < Bsz * Nsz * Dsz) { g_SV[i] = 0.f; g_T[i] = 0.f; }
}

// ---------------------------------------------------------------------------
// w: 256 thr/block, 32 rows/block. Centers live in registers (float4/thread).
// ---------------------------------------------------------------------------
__global__ void __launch_bounds__(256) compute_w_kernel(const float* __restrict__ x,
                                 const float* __restrict__ centers) {
    __shared__ float part[CW_ROWS][8][13];
    __shared__ float x2s[CW_ROWS];
    __shared__ float gs[CW_ROWS][Nsz];
    __shared__ float invs[CW_ROWS];

    int t = threadIdx.x, warp = t >> 5, lane = t & 31;
    size_t r0 = (size_t)blockIdx.x * CW_ROWS;

    float4 cf[Nsz];
    #pragma unroll
    for (int n = 0; n < Nsz; n++)
        cf[n] = *(const float4*)(centers + n * Dsz + t * 4);

    for (int r = 0; r < CW_ROWS; r++) {
        float4 xv = *(const float4*)(x + (r0 + r) * Dsz + t * 4);
        float p[13];
        p[12] = xv.x * xv.x + xv.y * xv.y + xv.z * xv.z + xv.w * xv.w;
        #pragma unroll
        for (int n = 0; n < Nsz; n++)
            p[n] = xv.x * cf[n].x + xv.y * cf[n].y + xv.z * cf[n].z + xv.w * cf[n].w;
        #pragma unroll
        for (int o = 16; o > 0; o >>= 1) {
            #pragma unroll
            for (int i = 0; i < 13; i++) p[i] += __shfl_down_sync(0xffffffffu, p[i], o);
        }
        if (lane == 0) {
            #pragma unroll
            for (int i = 0; i < 13; i++) part[r][warp][i] = p[i];
        }
    }
    __syncthreads();

    if (t < CW_ROWS) {
        float s = 0.f;
        #pragma unroll
        for (int w = 0; w < 8; w++) s += part[t][w][12];
        x2s[t] = s;
    }
    __syncthreads();

    for (int i = t; i < CW_ROWS * Nsz; i += 256) {
        int r = i / Nsz, n = i % Nsz;
        float xc = 0.f;
        #pragma unroll
        for (int w = 0; w < 8; w++) xc += part[r][w][n];
        float d2 = fmaxf(x2s[r] + g_params[n] - 2.f * xc, 0.f);
        gs[r][n] = __expf(-d2 * g_params[Nsz + n]) * g_params[2 * Nsz + n];
    }
    __syncthreads();

    if (t < CW_ROWS) {
        float s = 0.f;
        #pragma unroll
        for (int n = 0; n < Nsz; n++) s += gs[t][n];
        invs[t] = 1.f / fmaxf(s, 1e-8f);
    }
    __syncthreads();

    for (int i = t; i < CW_ROWS * Nsz; i += 256)
        g_w[r0 * Nsz + i] = gs[i / Nsz][i % Nsz] * invs[i / Nsz];
}

// ---------------------------------------------------------------------------
// Stage 1: Upart[sc,b,n,d] = sum_{s in chunk} w[b,s,n]*x[b,s,d]. No atomics.
// 256 thr cover full D via float4; w staged in smem (broadcast reads).
// ---------------------------------------------------------------------------
__global__ void __launch_bounds__(256) accum_U_s1(const float* __restrict__ x) {
    __shared__ float ws[SC_CHUNK * Nsz];  // 6 KB
    int sc = blockIdx.x;   // 0..63
    int b  = blockIdx.y;   // 0..3
    int t  = threadIdx.x;  // 256
    int s0 = sc * SC_CHUNK;

    const float* wg = g_w + ((size_t)(b * Ssz + s0)) * Nsz;
    for (int i = t; i < SC_CHUNK * Nsz; i += 256) ws[i] = wg[i];
    __syncthreads();

    const float* xb = x + ((size_t)(b * Ssz + s0)) * Dsz + t * 4;
    float4 acc[Nsz];
    #pragma unroll
    for (int n = 0; n < Nsz; n++) acc[n] = make_float4(0.f, 0.f, 0.f, 0.f);

    #pragma unroll 4
    for (int s = 0; s < SC_CHUNK; s++) {
        float4 xv = *(const float4*)(xb + (size_t)s * Dsz);
        #pragma unroll
        for (int n = 0; n < Nsz; n++) {
            float wv = ws[s * Nsz + n];
            acc[n].x += wv * xv.x; acc[n].y += wv * xv.y;
            acc[n].z += wv * xv.z; acc[n].w += wv * xv.w;
        }
    }
    float* up = g_Upart + ((size_t)(sc * Bsz + b) * Nsz) * Dsz + t * 4;
    #pragma unroll
    for (int n = 0; n < Nsz; n++) *(float4*)(up + n * Dsz) = acc[n];
}

// Stage 2: g_U[b,n,d] = sum_sc Upart
__global__ void accum_U_s2() {
    int idx = blockIdx.x * 256 + threadIdx.x;  // float4 index over 48*1024
    if (idx >= Bsz * Nsz * Dsz / 4) return;
    int d4 = idx & 255;
    int bn = idx >> 8;           // b*12+n
    int b = bn / Nsz, n = bn % Nsz;
    float4 s = make_float4(0.f, 0.f, 0.f, 0.f);
    #pragma unroll 8
    for (int sc = 0; sc < SC_NCHUNK; sc++) {
        float4 v = *(const float4*)(g_Upart + (((size_t)(sc * Bsz + b) * Nsz + n) << 10) + d4 * 4);
        s.x += v.x; s.y += v.y; s.z += v.z; s.w += v.w;
    }
    *(float4*)(g_U + ((size_t)bn << 10) + d4 * 4) = s;
}

// ---------------------------------------------------------------------------
// Tiny K-split GEMM: C[m,e] += sum_k A[m,k]*W[e,k], M=48, E=K=1024
// ---------------------------------------------------------------------------
__global__ void small_gemm_kernel(const float* __restrict__ W, int phase) {
    const float* A = phase ? g_SV : g_U;
    float* C = phase ? g_T : g_SV;
    __shared__ float As[64][49];
    __shared__ float Ws[64][66];
    int e0 = blockIdx.x * 64;
    int k0 = blockIdx.y * 64;
    int t = threadIdx.x;  // 256

    for (int idx = t; idx < 48 * 64; idx += 256) {
        int m = idx >> 6, kk = idx & 63;
        As[kk][m] = A[(size_t)m * Dsz + k0 + kk];
    }
    for (int idx = t; idx < 64 * 64; idx += 256) {
        int e = idx >> 6, kk = idx & 63;
        Ws[kk][e] = W[(size_t)(e0 + e) * Dsz + k0 + kk];
    }
    __syncthreads();

    int ty = t >> 5, tx = t & 31;
    float acc[6][2];
    #pragma unroll
    for (int i = 0; i < 6; i++) { acc[i][0] = 0.f; acc[i][1] = 0.f; }

    for (int kk = 0; kk < 64; kk++) {
        float a[6];
        #pragma unroll
        for (int i = 0; i < 6; i++) a[i] = As[kk][ty * 6 + i];
        float2 wv = *(const float2*)&Ws[kk][tx * 2];
        #pragma unroll
        for (int i = 0; i < 6; i++) {
            acc[i][0] += a[i] * wv.x;
            acc[i][1] += a[i] * wv.y;
        }
    }
    #pragma unroll
    for (int i = 0; i < 6; i++) {
        int m = ty * 6 + i;
        atomicAdd(&C[(size_t)m * Dsz + e0 + tx * 2 + 0], acc[i][0]);
        atomicAdd(&C[(size_t)m * Dsz + e0 + tx * 2 + 1], acc[i][1]);
    }
}

// ---------------------------------------------------------------------------
// final[b,s,:] = sum_n w[b,s,n] * T[b,n,:]
// ---------------------------------------------------------------------------
__global__ void expand_kernel(float* __restrict__ out) {
    __shared__ float Ts[Nsz][Dsz];  // 48 KB
    int b  = blockIdx.y;
    int r0 = blockIdx.x * 32;
    int t  = threadIdx.x;  // 256

    for (int idx = t; idx < Nsz * Dsz; idx += 256)
        Ts[idx >> 10][idx & 1023] = g_T[(size_t)b * Nsz * Dsz + idx];
    __syncthreads();

    int e = t * 4;
    for (int r = 0; r < 32; r++) {
        size_t row = (size_t)b * Ssz + r0 + r;
        const float* wr = g_w + row * Nsz;
        float4 o = make_float4(0.f, 0.f, 0.f, 0.f);
        #pragma unroll
        for (int n = 0; n < Nsz; n++) {
            float wv = __ldg(&wr[n]);
            float4 tv = *(const float4*)&Ts[n][e];
            o.x += wv * tv.x;
            o.y += wv * tv.y;
            o.z += wv * tv.z;
            o.w += wv * tv.w;
        }
        *(float4*)&out[row * Dsz + e] = o;
    }
}

extern "C" void kernel_launch(void* const* d_in, const int* in_sizes, int n_in,
                              void* d_out, int out_size) {
    const float* x        = (const float*)d_in[0];
    const float* centers  = (const float*)d_in[1];
    const float* scales   = (const float*)d_in[2];
    const float* amps     = (const float*)d_in[3];
    const float* w_value  = (const float*)d_in[4];
    const float* w_output = (const float*)d_in[5];
    float* out = (float*)d_out;

    prep_kernel<<<1, 384>>>(centers, scales, amps);
    zero_kernel<<<(Bsz * Nsz * Dsz + 255) / 256, 256>>>();
    compute_w_kernel<<<NROWS / CW_ROWS, 256>>>(x, centers);
    accum_U_s1<<<dim3(SC_NCHUNK, Bsz), 256>>>(x);
    accum_U_s2<<<(Bsz * Nsz * Dsz / 4 + 255) / 256, 256>>>();
    small_gemm_kernel<<<dim3(16, 16), 256>>>(w_value, 0);
    small_gemm_kernel<<<dim3(16, 16), 256>>>(w_output, 1);
    expand_kernel<<<dim3(Ssz / 32, Bsz), 256>>>(out);
}